// round 1
// baseline (speedup 1.0000x reference)
#include <cuda_runtime.h>

#define BB 8
#define CC 128
#define NN 4096
#define MM 1024
#define C8 16
#define C2 64

// ---------------- device scratch (no allocs allowed) ----------------
__device__ float g_theta[BB * C8 * NN];   // [b][c][n]
__device__ float g_phi  [BB * C8 * MM];   // [b][c][m]
__device__ float g_gv   [BB * C2 * MM];   // [b][c][m]

// =====================================================================
// Kernel 1: fused 1x1-conv projections (theta/phi/g) + 2x2 maxpool
// One CTA handles one batch and one pooled row h (rows 2h, 2h+1 of x,
// which are 128 CONTIGUOUS floats per channel since n = row*64 + col).
// =====================================================================
__global__ __launch_bounds__(256) void proj_kernel(
    const float* __restrict__ x,
    const float* __restrict__ Wt,
    const float* __restrict__ Wp,
    const float* __restrict__ Wg)
{
    extern __shared__ float sm[];
    float* Wc = sm;                      // [96][128]  rows 0-15 Wt, 16-31 Wp, 32-95 Wg
    float* xs = sm + 96 * 128;           // [128][128] channel-major tile
    float* P  = sm + (96 + 128) * 128;   // [96][128]  projected tile

    const int b = blockIdx.y;
    const int h = blockIdx.x;            // pooled row 0..31
    const int t = threadIdx.x;

    for (int i = t; i < 16 * 128; i += 256) Wc[i]            = Wt[i];
    for (int i = t; i < 16 * 128; i += 256) Wc[16*128 + i]   = Wp[i];
    for (int i = t; i < 64 * 128; i += 256) Wc[32*128 + i]   = Wg[i];

    const float* xb = x + ((size_t)b * CC) * NN + h * 128;
    for (int i = t; i < 128 * 32; i += 256) {          // 128 ch * 32 float4
        int c  = i >> 5;
        int p4 = (i & 31) << 2;
        *(float4*)&xs[c * 128 + p4] =
            *(const float4*)&xb[(size_t)c * NN + p4];
    }
    __syncthreads();

    // GEMM: P[o][px] = sum_c Wc[o][c] * xs[c][px]
    const int pi = t & 31;   // px block (4 px, float4)
    const int og = t >> 5;   // 0..7 -> 12 output rows each (8*12 = 96)
    float acc[12][4];
    #pragma unroll
    for (int k = 0; k < 12; k++) { acc[k][0]=acc[k][1]=acc[k][2]=acc[k][3]=0.f; }

    for (int c = 0; c < 128; c++) {
        float4 xv = *(const float4*)&xs[c * 128 + pi * 4];
        #pragma unroll
        for (int k = 0; k < 12; k++) {
            float w = Wc[(og * 12 + k) * 128 + c];     // broadcast in warp
            acc[k][0] += w * xv.x; acc[k][1] += w * xv.y;
            acc[k][2] += w * xv.z; acc[k][3] += w * xv.w;
        }
    }
    #pragma unroll
    for (int k = 0; k < 12; k++) {
        float4 v = make_float4(acc[k][0], acc[k][1], acc[k][2], acc[k][3]);
        *(float4*)&P[(og * 12 + k) * 128 + pi * 4] = v;
    }
    __syncthreads();

    // theta (no pooling): n = 128h + px
    float* thb = g_theta + (size_t)b * C8 * NN + h * 128;
    for (int i = t; i < 16 * 128; i += 256) {
        int o = i >> 7, px = i & 127;
        thb[(size_t)o * NN + px] = P[o * 128 + px];
    }
    // phi pooled: block wp covers px {2wp, 2wp+1, 64+2wp, 65+2wp}; m = 32h + wp
    float* phb = g_phi + (size_t)b * C8 * MM + h * 32;
    for (int i = t; i < 16 * 32; i += 256) {
        int o = i >> 5, wp = i & 31;
        const float* Pr = &P[(16 + o) * 128];
        float v = fmaxf(fmaxf(Pr[2*wp], Pr[2*wp + 1]),
                        fmaxf(Pr[64 + 2*wp], Pr[64 + 2*wp + 1]));
        phb[(size_t)o * MM + wp] = v;
    }
    // g pooled
    float* ggb = g_gv + (size_t)b * C2 * MM + h * 32;
    for (int i = t; i < 64 * 32; i += 256) {
        int o = i >> 5, wp = i & 31;
        const float* Pr = &P[(32 + o) * 128];
        float v = fmaxf(fmaxf(Pr[2*wp], Pr[2*wp + 1]),
                        fmaxf(Pr[64 + 2*wp], Pr[64 + 2*wp + 1]));
        ggb[(size_t)o * MM + wp] = v;
    }
}

// =====================================================================
// Kernel 2: fused attention. One CTA = (batch, 128-query tile).
// Single-pass softmax (logits bounded ~|8| -> no max subtraction needed):
//   o[c][n] = (sum_m exp(s[n][m]) * g[c][m]) / (sum_m exp(s[n][m]))
// then out = gamma * (Wo @ o) + x, fully fused.
// =====================================================================
#define TMCH 128
#define TMP  129    // odd pad: conflict-free column access
#define PHIP 20     // 16 ch + pad, 80B rows (float4 aligned)
#define OPAD 132
#define WOPAD 65

#define OFF_PHI  0
#define OFF_G    (128 * PHIP)              // 2560
#define OFF_P    (OFF_G + 64 * TMP)        // 10816
#define OFF_DEN  (OFF_P + 128 * TMP)       // 27328
#define OFF_RDEN (OFF_DEN + 128)           // 27456
#define SM2_FLOATS (OFF_RDEN + 128)        // 27584 floats = 110336 B
// aliases (post-mainloop): o_s[64][132]=8448 fl at 0 (over phi+g, <=10816 OK)
//                          Wo_s[128][65]=8320 fl at OFF_P (over p_s, <=16512 OK)

__global__ __launch_bounds__(256) void attn_kernel(
    const float* __restrict__ Wo,
    const float* __restrict__ x,
    const float* __restrict__ gamma_p,
    float* __restrict__ out)
{
    extern __shared__ float sm[];
    float* phi_t = sm + OFF_PHI;   // [128 m][20]  (transposed, broadcast reads)
    float* g_s   = sm + OFF_G;     // [64 c][129]
    float* p_s   = sm + OFF_P;     // [128 n][129]
    float* den   = sm + OFF_DEN;   // [128]
    float* rden  = sm + OFF_RDEN;  // [128]
    float* o_s   = sm;             // alias [64][132]
    float* Wo_s  = sm + OFF_P;     // alias [128][65]

    const int b  = blockIdx.y;
    const int n0 = blockIdx.x * 128;
    const int t  = threadIdx.x;

    if (t < 128) den[t] = 0.f;

    // logits-phase mapping: thread owns query tq, key half mg
    const int tq = t & 127, mg = t >> 7;
    const float* thb = g_theta + (size_t)b * C8 * NN + n0 + tq;
    float th[16];
    #pragma unroll
    for (int c = 0; c < 16; c++) th[c] = thb[(size_t)c * NN];

    // accumulate-phase mapping: 4 c-rows x 8 n-cols per thread
    const int ci = t & 15, nj = t >> 4;
    float acc[4][8];
    #pragma unroll
    for (int a = 0; a < 4; a++)
        #pragma unroll
        for (int e = 0; e < 8; e++) acc[a][e] = 0.f;

    const float* phib = g_phi + (size_t)b * C8 * MM;
    const float* gb   = g_gv  + (size_t)b * C2 * MM;

    for (int m0 = 0; m0 < MM; m0 += TMCH) {
        __syncthreads();   // covers den init + previous-chunk smem reads
        // load phi chunk transposed: [m][c]
        for (int i = t; i < 16 * 128; i += 256) {
            int c = i >> 7, m = i & 127;
            phi_t[m * PHIP + c] = phib[(size_t)c * MM + m0 + m];
        }
        // load g chunk: [c][m]
        for (int i = t; i < 64 * 128; i += 256) {
            int c = i >> 7, m = i & 127;
            g_s[c * TMP + m] = gb[(size_t)c * MM + m0 + m];
        }
        __syncthreads();

        // logits + exp + p to smem + denom
        float dsum = 0.f;
        for (int k = 0; k < 64; k++) {
            int m = mg * 64 + k;
            const float4* pr = (const float4*)&phi_t[m * PHIP];
            float4 f0 = pr[0], f1 = pr[1], f2 = pr[2], f3 = pr[3];
            float s = th[0]*f0.x + th[1]*f0.y + th[2]*f0.z + th[3]*f0.w
                    + th[4]*f1.x + th[5]*f1.y + th[6]*f1.z + th[7]*f1.w
                    + th[8]*f2.x + th[9]*f2.y + th[10]*f2.z + th[11]*f2.w
                    + th[12]*f3.x + th[13]*f3.y + th[14]*f3.z + th[15]*f3.w;
            float p = __expf(s);
            p_s[tq * TMP + m] = p;
            dsum += p;
        }
        atomicAdd(&den[tq], dsum);
        __syncthreads();

        // acc[c][n] += g[c][m] * p[n][m]   (32 FMA / 12 LDS per m)
        #pragma unroll 2
        for (int m = 0; m < TMCH; m++) {
            float gv[4], pv[8];
            #pragma unroll
            for (int a = 0; a < 4; a++) gv[a] = g_s[(4 * ci + a) * TMP + m];
            #pragma unroll
            for (int e = 0; e < 8; e++) pv[e] = p_s[(8 * nj + e) * TMP + m];
            #pragma unroll
            for (int a = 0; a < 4; a++)
                #pragma unroll
                for (int e = 0; e < 8; e++)
                    acc[a][e] += gv[a] * pv[e];
        }
    }
    __syncthreads();

    // epilogue setup: reciprocal denom + Wo into smem (aliases p_s, now dead)
    if (t < 128) rden[t] = 1.0f / den[t];
    for (int i = t; i < 128 * 64; i += 256) {
        int co = i >> 6, c = i & 63;
        Wo_s[co * WOPAD + c] = Wo[i];
    }
    __syncthreads();

    // normalized o into smem (aliases phi_t/g_s, now dead)
    #pragma unroll
    for (int a = 0; a < 4; a++)
        #pragma unroll
        for (int e = 0; e < 8; e++)
            o_s[(4 * ci + a) * OPAD + 8 * nj + e] = acc[a][e] * rden[8 * nj + e];
    __syncthreads();

    // out[co][n] = gamma * sum_c Wo[co][c] * o[c][n] + x[co][n]
    const float gm = *gamma_p;
    const int nj2 = t & 15, ci2 = t >> 4;   // n fast across warp -> coalesced stores
    for (int nh = 0; nh < 2; nh++) {
        float ea[8][4];
        #pragma unroll
        for (int kk = 0; kk < 8; kk++) { ea[kk][0]=ea[kk][1]=ea[kk][2]=ea[kk][3]=0.f; }
        for (int c = 0; c < 64; c++) {
            float4 ov = *(const float4*)&o_s[c * OPAD + nh * 64 + nj2 * 4];
            #pragma unroll
            for (int kk = 0; kk < 8; kk++) {
                float w = Wo_s[(8 * ci2 + kk) * WOPAD + c];
                ea[kk][0] += w * ov.x; ea[kk][1] += w * ov.y;
                ea[kk][2] += w * ov.z; ea[kk][3] += w * ov.w;
            }
        }
        #pragma unroll
        for (int kk = 0; kk < 8; kk++) {
            int co = 8 * ci2 + kk;
            int n  = n0 + nh * 64 + nj2 * 4;
            const float4 xv = *(const float4*)&x[((size_t)b * CC + co) * NN + n];
            float4 r;
            r.x = gm * ea[kk][0] + xv.x;
            r.y = gm * ea[kk][1] + xv.y;
            r.z = gm * ea[kk][2] + xv.z;
            r.w = gm * ea[kk][3] + xv.w;
            *(float4*)&out[((size_t)b * CC + co) * NN + n] = r;
        }
    }
}

// =====================================================================
extern "C" void kernel_launch(void* const* d_in, const int* in_sizes, int n_in,
                              void* d_out, int out_size)
{
    (void)in_sizes; (void)n_in; (void)out_size;
    const float* x  = (const float*)d_in[0];
    const float* Wt = (const float*)d_in[1];
    const float* Wp = (const float*)d_in[2];
    const float* Wg = (const float*)d_in[3];
    const float* Wo = (const float*)d_in[4];
    const float* gm = (const float*)d_in[5];
    float* out = (float*)d_out;

    const int smem1 = 320 * 128 * 4;        // 163840 B
    const int smem2 = SM2_FLOATS * 4;       // 110336 B
    cudaFuncSetAttribute(proj_kernel, cudaFuncAttributeMaxDynamicSharedMemorySize, smem1);
    cudaFuncSetAttribute(attn_kernel, cudaFuncAttributeMaxDynamicSharedMemorySize, smem2);

    proj_kernel<<<dim3(32, BB), 256, smem1>>>(x, Wt, Wp, Wg);
    attn_kernel<<<dim3(32, BB), 256, smem2>>>(Wo, x, gm, out);
}

// round 5
// speedup vs baseline: 2.4068x; 2.4068x over previous
#include <cuda_runtime.h>
#include <cstdint>

#define BB 8
#define CC 128
#define NN 4096
#define MM 1024
#define C2 64
#define LOG2E 1.4426950408889634f

// ---------------- device scratch (no allocs allowed) ----------------
__device__ float g_theta[BB * NN * 16];   // [b][n][c]  c fast
__device__ float g_phi  [BB * MM * 16];   // [b][m][c]  c fast
__device__ float g_gv   [BB * C2 * MM];   // [b][c][m]  m fast

// m16n8k8 tf32 mma (arch-generic PTX sm_80+, legacy-HMMA path on sm_100 base target)
__device__ __forceinline__ void mma_tf32(
    float& c0, float& c1, float& c2, float& c3,
    uint32_t a0, uint32_t a1, uint32_t a2, uint32_t a3,
    uint32_t b0, uint32_t b1)
{
    asm volatile(
        "mma.sync.aligned.m16n8k8.row.col.f32.tf32.tf32.f32 "
        "{%0,%1,%2,%3}, {%4,%5,%6,%7}, {%8,%9}, {%0,%1,%2,%3};"
        : "+f"(c0), "+f"(c1), "+f"(c2), "+f"(c3)
        : "r"(a0), "r"(a1), "r"(a2), "r"(a3), "r"(b0), "r"(b1));
}
__device__ __forceinline__ float ex2(float x) {
    float y;
    asm("ex2.approx.f32 %0, %1;" : "=f"(y) : "f"(x));
    return y;
}

// =====================================================================
// Kernel 1: fused 1x1-conv projections (theta/phi/g) + 2x2 maxpool
// One CTA = (batch, pooled row pair). x rows 2h,2h+1 are 128 contiguous
// floats per channel (n = row*64 + col).
// =====================================================================
__global__ __launch_bounds__(256) void proj_kernel(
    const float* __restrict__ x,
    const float* __restrict__ Wt,
    const float* __restrict__ Wp,
    const float* __restrict__ Wg)
{
    extern __shared__ float sm[];
    float* Wc = sm;                      // [96][128]
    float* xs = sm + 96 * 128;           // [128][128]
    float* P  = sm + (96 + 128) * 128;   // [96][128]

    const int b = blockIdx.y;
    const int h = blockIdx.x;            // pooled row 0..31
    const int t = threadIdx.x;

    for (int i = t; i < 16 * 128; i += 256) Wc[i]          = Wt[i];
    for (int i = t; i < 16 * 128; i += 256) Wc[16*128 + i] = Wp[i];
    for (int i = t; i < 64 * 128; i += 256) Wc[32*128 + i] = Wg[i];

    const float* xb = x + ((size_t)b * CC) * NN + h * 128;
    for (int i = t; i < 128 * 32; i += 256) {
        int c  = i >> 5;
        int p4 = (i & 31) << 2;
        *(float4*)&xs[c * 128 + p4] = *(const float4*)&xb[(size_t)c * NN + p4];
    }
    __syncthreads();

    const int pi = t & 31;
    const int og = t >> 5;
    float acc[12][4];
    #pragma unroll
    for (int k = 0; k < 12; k++) { acc[k][0]=acc[k][1]=acc[k][2]=acc[k][3]=0.f; }

    for (int c = 0; c < 128; c++) {
        float4 xv = *(const float4*)&xs[c * 128 + pi * 4];
        #pragma unroll
        for (int k = 0; k < 12; k++) {
            float w = Wc[(og * 12 + k) * 128 + c];
            acc[k][0] += w * xv.x; acc[k][1] += w * xv.y;
            acc[k][2] += w * xv.z; acc[k][3] += w * xv.w;
        }
    }
    #pragma unroll
    for (int k = 0; k < 12; k++)
        *(float4*)&P[(og * 12 + k) * 128 + pi * 4] =
            make_float4(acc[k][0], acc[k][1], acc[k][2], acc[k][3]);
    __syncthreads();

    // theta: [b][n][16]  (c fast)
    float* thb = g_theta + ((size_t)b * NN + h * 128) * 16;
    for (int i = t; i < 16 * 128; i += 256) {
        int o = i & 15, px = i >> 4;
        thb[i] = P[o * 128 + px];
    }
    // phi pooled: [b][m][16]
    float* phb = g_phi + ((size_t)b * MM + h * 32) * 16;
    for (int i = t; i < 512; i += 256) {
        int o = i & 15, wp = i >> 4;
        const float* Pr = &P[(16 + o) * 128];
        float v = fmaxf(fmaxf(Pr[2*wp], Pr[2*wp + 1]),
                        fmaxf(Pr[64 + 2*wp], Pr[65 + 2*wp]));
        phb[i] = v;
    }
    // g pooled: [b][c][m]
    float* ggb = g_gv + (size_t)b * C2 * MM + h * 32;
    for (int i = t; i < 64 * 32; i += 256) {
        int o = i >> 5, wp = i & 31;
        const float* Pr = &P[(32 + o) * 128];
        float v = fmaxf(fmaxf(Pr[2*wp], Pr[2*wp + 1]),
                        fmaxf(Pr[64 + 2*wp], Pr[65 + 2*wp]));
        ggb[(size_t)o * MM + wp] = v;
    }
}

// =====================================================================
// Kernel 2: mma.sync tf32 flash attention + Wo epilogue.
// One CTA = (batch, 128-query tile), 8 warps. Each warp owns 16 rows.
// Single-pass softmax (logits bounded -> exp without max subtraction).
// =====================================================================
// SMEM layout (floats):
#define PH_PITCH 20
#define GS_PITCH 132
#define PS_PITCH 132
#define OFF_GS   (128 * PH_PITCH)                 // 2560
#define OFF_PS   (OFF_GS + 64 * GS_PITCH)         // 11008
#define SM_FLOATS (OFF_PS + 8 * 16 * PS_PITCH)    // 27904 -> 111616 B
// epilogue aliases: wo_s [128][68] at 0 (<= 11008 ok), o_s [8][16][68] at OFF_PS

__global__ __launch_bounds__(256) void attn_mma(
    const float* __restrict__ Wo,
    const float* __restrict__ x,
    const float* __restrict__ gamma_p,
    float* __restrict__ out)
{
    extern __shared__ float sm[];
    float* ph_s = sm;                 // [128][20]
    float* g_s  = sm + OFF_GS;        // [64][132]
    float* p_s  = sm + OFF_PS;        // [8][16][132]
    float* wo_s = sm;                 // alias [128][68]
    float* o_s  = sm + OFF_PS;        // alias [8][16][68]

    const int t = threadIdx.x, w = t >> 5, lane = t & 31;
    const int g = lane >> 2, tg = lane & 3;
    const int b = blockIdx.y, n0 = blockIdx.x * 128;

    // theta A-fragments (constant for whole kernel), pre-scaled by log2(e)
    const float* thg = g_theta + ((size_t)b * NN + n0 + w * 16) * 16;
    uint32_t aTh[2][4];
    #pragma unroll
    for (int ks = 0; ks < 2; ks++) {
        aTh[ks][0] = __float_as_uint(thg[(g    ) * 16 + ks * 8 + tg    ] * LOG2E);
        aTh[ks][1] = __float_as_uint(thg[(g + 8) * 16 + ks * 8 + tg    ] * LOG2E);
        aTh[ks][2] = __float_as_uint(thg[(g    ) * 16 + ks * 8 + tg + 4] * LOG2E);
        aTh[ks][3] = __float_as_uint(thg[(g + 8) * 16 + ks * 8 + tg + 4] * LOG2E);
    }

    float oacc[8][4];
    #pragma unroll
    for (int ct = 0; ct < 8; ct++) { oacc[ct][0]=oacc[ct][1]=oacc[ct][2]=oacc[ct][3]=0.f; }
    float ds0 = 0.f, ds1 = 0.f;   // row-sum partials (rows w*16+g, w*16+g+8)

    const float* phg = g_phi + (size_t)b * MM * 16;
    const float* gg  = g_gv  + (size_t)b * C2 * MM;
    float* pw = p_s + w * 16 * PS_PITCH;

    for (int ch = 0; ch < 8; ch++) {
        __syncthreads();
        // load phi chunk [128m][16c] -> pitch 20
        {
            const float4* src = (const float4*)(phg + (size_t)ch * 128 * 16);
            for (int i = t; i < 512; i += 256) {
                int m = i >> 2, q = i & 3;
                *(float4*)&ph_s[m * PH_PITCH + q * 4] = src[i];
            }
        }
        // load g chunk [64c][128m] -> pitch 132
        for (int i = t; i < 2048; i += 256) {
            int c = i >> 5, m4 = (i & 31) * 4;
            *(float4*)&g_s[c * GS_PITCH + m4] =
                *(const float4*)&gg[(size_t)c * MM + ch * 128 + m4];
        }
        __syncthreads();

        // ---- phase A: S = theta*phi^T, exp2 in-register, P -> warp-private smem
        #pragma unroll
        for (int mt = 0; mt < 16; mt++) {
            float c0 = 0.f, c1 = 0.f, c2 = 0.f, c3 = 0.f;
            #pragma unroll
            for (int ks = 0; ks < 2; ks++) {
                uint32_t b0 = __float_as_uint(ph_s[(mt * 8 + g) * PH_PITCH + ks * 8 + tg    ]);
                uint32_t b1 = __float_as_uint(ph_s[(mt * 8 + g) * PH_PITCH + ks * 8 + tg + 4]);
                mma_tf32(c0, c1, c2, c3, aTh[ks][0], aTh[ks][1], aTh[ks][2], aTh[ks][3], b0, b1);
            }
            c0 = ex2(c0); c1 = ex2(c1); c2 = ex2(c2); c3 = ex2(c3);
            ds0 += c0 + c1; ds1 += c2 + c3;
            *(float2*)&pw[(g    ) * PS_PITCH + mt * 8 + 2 * tg] = make_float2(c0, c1);
            *(float2*)&pw[(g + 8) * PS_PITCH + mt * 8 + 2 * tg] = make_float2(c2, c3);
        }
        // p_s rows are warp-private: no block sync needed before phase B

        // ---- phase B: O += P * G^T  (contraction over 128 m, 16 ksteps)
        #pragma unroll 4
        for (int kt = 0; kt < 16; kt++) {
            uint32_t a0 = __float_as_uint(pw[(g    ) * PS_PITCH + kt * 8 + tg    ]);
            uint32_t a1 = __float_as_uint(pw[(g + 8) * PS_PITCH + kt * 8 + tg    ]);
            uint32_t a2 = __float_as_uint(pw[(g    ) * PS_PITCH + kt * 8 + tg + 4]);
            uint32_t a3 = __float_as_uint(pw[(g + 8) * PS_PITCH + kt * 8 + tg + 4]);
            #pragma unroll
            for (int ct = 0; ct < 8; ct++) {
                uint32_t b0 = __float_as_uint(g_s[(ct * 8 + g) * GS_PITCH + kt * 8 + tg    ]);
                uint32_t b1 = __float_as_uint(g_s[(ct * 8 + g) * GS_PITCH + kt * 8 + tg + 4]);
                mma_tf32(oacc[ct][0], oacc[ct][1], oacc[ct][2], oacc[ct][3],
                         a0, a1, a2, a3, b0, b1);
            }
        }
    }

    // ---- softmax denominators: reduce over the 4 lanes of each quad
    ds0 += __shfl_xor_sync(0xffffffff, ds0, 1);
    ds0 += __shfl_xor_sync(0xffffffff, ds0, 2);
    ds1 += __shfl_xor_sync(0xffffffff, ds1, 1);
    ds1 += __shfl_xor_sync(0xffffffff, ds1, 2);
    const float r0 = 1.0f / ds0, r1 = 1.0f / ds1;

    __syncthreads();   // all warps done with g_s/ph_s before aliasing

    // normalized o -> o_s (warp-private rows), Wo -> wo_s
    float* ow = o_s + w * 16 * 68;
    #pragma unroll
    for (int ct = 0; ct < 8; ct++) {
        *(float2*)&ow[(g    ) * 68 + ct * 8 + 2 * tg] =
            make_float2(oacc[ct][0] * r0, oacc[ct][1] * r0);
        *(float2*)&ow[(g + 8) * 68 + ct * 8 + 2 * tg] =
            make_float2(oacc[ct][2] * r1, oacc[ct][3] * r1);
    }
    for (int i = t; i < 2048; i += 256) {
        int co = i >> 4, c4 = (i & 15) * 4;
        *(float4*)&wo_s[co * 68 + c4] = *(const float4*)&Wo[co * 64 + c4];
    }
    __syncthreads();

    // ---- epilogue GEMM: D = o_norm * Wo^T, out = gamma*D + x
    uint32_t aEp[8][4];
    #pragma unroll
    for (int kt = 0; kt < 8; kt++) {
        aEp[kt][0] = __float_as_uint(ow[(g    ) * 68 + kt * 8 + tg    ]);
        aEp[kt][1] = __float_as_uint(ow[(g + 8) * 68 + kt * 8 + tg    ]);
        aEp[kt][2] = __float_as_uint(ow[(g    ) * 68 + kt * 8 + tg + 4]);
        aEp[kt][3] = __float_as_uint(ow[(g + 8) * 68 + kt * 8 + tg + 4]);
    }
    const float gm = *gamma_p;
    const int nr0 = n0 + w * 16 + g, nr1 = nr0 + 8;
    #pragma unroll
    for (int ot = 0; ot < 16; ot++) {
        float d0 = 0.f, d1 = 0.f, d2 = 0.f, d3 = 0.f;
        #pragma unroll
        for (int kt = 0; kt < 8; kt++) {
            uint32_t b0 = __float_as_uint(wo_s[(ot * 8 + g) * 68 + kt * 8 + tg    ]);
            uint32_t b1 = __float_as_uint(wo_s[(ot * 8 + g) * 68 + kt * 8 + tg + 4]);
            mma_tf32(d0, d1, d2, d3, aEp[kt][0], aEp[kt][1], aEp[kt][2], aEp[kt][3], b0, b1);
        }
        const int co = ot * 8 + 2 * tg;
        size_t i00 = ((size_t)b * CC + co) * NN + nr0;
        size_t i10 = ((size_t)b * CC + co) * NN + nr1;
        out[i00]      = fmaf(gm, d0, x[i00]);
        out[i00 + NN] = fmaf(gm, d1, x[i00 + NN]);
        out[i10]      = fmaf(gm, d2, x[i10]);
        out[i10 + NN] = fmaf(gm, d3, x[i10 + NN]);
    }
}

// =====================================================================
extern "C" void kernel_launch(void* const* d_in, const int* in_sizes, int n_in,
                              void* d_out, int out_size)
{
    (void)in_sizes; (void)n_in; (void)out_size;
    const float* x  = (const float*)d_in[0];
    const float* Wt = (const float*)d_in[1];
    const float* Wp = (const float*)d_in[2];
    const float* Wg = (const float*)d_in[3];
    const float* Wo = (const float*)d_in[4];
    const float* gm = (const float*)d_in[5];
    float* out = (float*)d_out;

    const int smem1 = 320 * 128 * 4;        // 163840
    const int smem2 = SM_FLOATS * 4;        // 111616
    cudaFuncSetAttribute(proj_kernel, cudaFuncAttributeMaxDynamicSharedMemorySize, smem1);
    cudaFuncSetAttribute(attn_mma,    cudaFuncAttributeMaxDynamicSharedMemorySize, smem2);

    proj_kernel<<<dim3(32, BB), 256, smem1>>>(x, Wt, Wp, Wg);
    attn_mma<<<dim3(32, BB), 256, smem2>>>(Wo, x, gm, out);
}